// round 13
// baseline (speedup 1.0000x reference)
#include <cuda_runtime.h>
#include <cuda_bf16.h>

#define B 4096
#define G 512
#define D 64
#define P (G * D)
#define EPS 1e-5f
#define NEG_SLOPE 0.2f

#define BT 1024             // number of b-tiles (4 rows each)

// scratch
__device__ float g_reps[(size_t)B * G];       // [B, G] row-major, 8 MB
__device__ float g_bsum [BT][G];              // per-btile partial sums  (2 MB)
__device__ float g_bsum2[BT][G];              // per-btile partial sumsq (2 MB)
__device__ float g_a[G];
__device__ float g_csum_part[16];             // per-k2-block partial sum of c[g]

// L2 evict-last store via cache-hint policy register (sm_103-legal encoding).
__device__ __forceinline__ unsigned long long mk_evict_last_policy() {
    unsigned long long pol;
    asm volatile("createpolicy.fractional.L2::evict_last.b64 %0, 1.0;" : "=l"(pol));
    return pol;
}
__device__ __forceinline__ void st_evict_last(float* p, float v,
                                              unsigned long long pol) {
    asm volatile("st.global.L2::cache_hint.f32 [%0], %1, %2;"
                 :: "l"(p), "f"(v), "l"(pol) : "memory");
}

// ---------------------------------------------------------------------------
// Kernel 1: reps[b,g] = leakyrelu( dot(x[b, g*64 : g*64+64], W[g]) )
// idx is identity (arange) by construction -> direct addressing.
// Block = (btile, gtile): 4 b-rows x 64 groups (halved from 8 rows: shorter
// block duration -> smaller end-of-grid drain at partial HBM utilization).
// W slice register-resident; 4 threads per group; 2-step segmented shfl
// reduce; per-btile partial stats, deterministic, no atomics.
// x streamed once (__ldcs, evict-first); reps/bsum stored evict-last.
// ---------------------------------------------------------------------------
__global__ void __launch_bounds__(256) k1_reps(
    const float* __restrict__ x,
    const float* __restrict__ W)
{
    const int t     = threadIdx.x;
    const int q     = t & 3;                       // slot phase within group
    const int btile = blockIdx.x >> 3;             // 0..1023
    const int gtile = blockIdx.x & 7;              // 0..7
    const int g     = (gtile << 6) + (t >> 2);     // group id
    const int b0    = btile << 2;                  // first of 4 rows

    const unsigned long long pol = mk_evict_last_policy();

    // W slice for this group: 64 floats = 4 float4, register-resident
    const float4* wp = (const float4*)(W + g * D) + q;
    const float4 w0 = __ldg(wp);
    const float4 w1 = __ldg(wp + 4);
    const float4 w2 = __ldg(wp + 8);
    const float4 w3 = __ldg(wp + 12);

    float s = 0.0f, s2 = 0.0f;

    #pragma unroll 2
    for (int i = 0; i < 4; ++i) {
        const int b = b0 + i;
        const float4* xp = (const float4*)(x + (size_t)b * P + g * D) + q;
        const float4 x0 = __ldcs(xp);
        const float4 x1 = __ldcs(xp + 4);
        const float4 x2 = __ldcs(xp + 8);
        const float4 x3 = __ldcs(xp + 12);

        float a0 = fmaf(x0.x, w0.x, x0.y * w0.y);
        a0 = fmaf(x0.z, w0.z, a0); a0 = fmaf(x0.w, w0.w, a0);
        float a1 = fmaf(x1.x, w1.x, x1.y * w1.y);
        a1 = fmaf(x1.z, w1.z, a1); a1 = fmaf(x1.w, w1.w, a1);
        float a2 = fmaf(x2.x, w2.x, x2.y * w2.y);
        a2 = fmaf(x2.z, w2.z, a2); a2 = fmaf(x2.w, w2.w, a2);
        float a3 = fmaf(x3.x, w3.x, x3.y * w3.y);
        a3 = fmaf(x3.z, w3.z, a3); a3 = fmaf(x3.w, w3.w, a3);

        float acc = (a0 + a1) + (a2 + a3);
        // butterfly over the 4-lane segment: all 4 lanes get the full dot
        acc += __shfl_xor_sync(0xffffffffu, acc, 1);
        acc += __shfl_xor_sync(0xffffffffu, acc, 2);

        acc = (acc >= 0.0f) ? acc : NEG_SLOPE * acc;
        if (q == 0) st_evict_last(&g_reps[(size_t)b * G + g], acc, pol);

        s  += acc;
        s2 += acc * acc;
    }

    if (q == 0) {
        st_evict_last(&g_bsum [btile][g], s,  pol);
        st_evict_last(&g_bsum2[btile][g], s2, pol);
    }
}

// ---------------------------------------------------------------------------
// Kernel 2: reduce 1024 per-btile partials per group -> a[g]; also emit this
// block's partial sum of c[g] (c folded out of k3's inner loop).
// grid = 16 blocks x 32 groups; 512 threads: lane = group (coalesced),
// 16 warps stride the btile dimension. Deterministic fixed-order reduction.
// logit[b] = sum_g a[g]*reps[b,g] + sum_g c[g] + fc_b
// ---------------------------------------------------------------------------
__global__ void __launch_bounds__(512) k2_stats(
    const float* __restrict__ gamma,
    const float* __restrict__ beta,
    const float* __restrict__ fc_w)
{
    cudaGridDependencySynchronize();   // PDL: wait for k1 results

    const int lane = threadIdx.x & 31;
    const int w    = threadIdx.x >> 5;           // 0..15
    const int g    = blockIdx.x * 32 + lane;

    float s = 0.0f, s2 = 0.0f;
    #pragma unroll 8
    for (int bt = w; bt < BT; bt += 16) {
        s  += g_bsum [bt][g];
        s2 += g_bsum2[bt][g];
    }

    __shared__ float sh[16][32];
    __shared__ float sh2[16][32];
    sh[w][lane] = s; sh2[w][lane] = s2;
    __syncthreads();

    if (w == 0) {
        float a = 0.0f, a2 = 0.0f;
        #pragma unroll
        for (int i = 0; i < 16; i++) { a += sh[i][lane]; a2 += sh2[i][lane]; }
        float mean = a * (1.0f / B);
        float var  = a2 * (1.0f / B) - mean * mean;
        float inv  = rsqrtf(var + EPS);
        float fw   = fc_w[g];
        float gm   = gamma[g];
        g_a[g] = fw * gm * inv;
        float c = fw * (beta[g] - gm * mean * inv);
        // partial sum of c over this block's 32 groups
        #pragma unroll
        for (int o = 16; o > 0; o >>= 1)
            c += __shfl_xor_sync(0xffffffffu, c, o);
        if (lane == 0) g_csum_part[blockIdx.x] = c;
    }
}

// ---------------------------------------------------------------------------
// Kernel 3: logit[b] = sum_g a[g]*reps[b,g] (+ csum + fc_b), sigmoid.
// 2 b-rows per warp (b and b+2048), grid = 256 blocks (proven R6 shape).
// ---------------------------------------------------------------------------
__global__ void __launch_bounds__(256) k3_out(
    const float* __restrict__ fc_b,
    float* __restrict__ out)
{
    cudaGridDependencySynchronize();   // PDL: wait for k2 (and k1) results

    const int lane = threadIdx.x & 31;
    const int w    = threadIdx.x >> 5;
    const int b    = blockIdx.x * 8 + w;          // 0..2047
    const int b2   = b + 2048;

    const float4* r4a = (const float4*)(g_reps + (size_t)b  * G);
    const float4* r4b = (const float4*)(g_reps + (size_t)b2 * G);
    const float4* a4  = (const float4*)g_a;

    float acc1 = 0.0f, acc2 = 0.0f;
    #pragma unroll
    for (int i = 0; i < 4; ++i) {
        const int j = i * 32 + lane;
        const float4 a  = __ldg(a4 + j);
        const float4 ra = __ldg(r4a + j);
        const float4 rb = __ldg(r4b + j);
        acc1 = fmaf(a.x, ra.x, acc1); acc2 = fmaf(a.x, rb.x, acc2);
        acc1 = fmaf(a.y, ra.y, acc1); acc2 = fmaf(a.y, rb.y, acc2);
        acc1 = fmaf(a.z, ra.z, acc1); acc2 = fmaf(a.z, rb.z, acc2);
        acc1 = fmaf(a.w, ra.w, acc1); acc2 = fmaf(a.w, rb.w, acc2);
    }

    // fold the c-sum partials (16 values) into both reductions
    if (lane < 16) {
        const float cp = g_csum_part[lane];
        acc1 += cp;
        acc2 += cp;
    }

    #pragma unroll
    for (int o = 16; o > 0; o >>= 1) {
        acc1 += __shfl_xor_sync(0xffffffffu, acc1, o);
        acc2 += __shfl_xor_sync(0xffffffffu, acc2, o);
    }

    if (lane == 0) {
        const float bias = fc_b[0];
        out[b]  = 1.0f / (1.0f + expf(-(acc1 + bias)));
        out[b2] = 1.0f / (1.0f + expf(-(acc2 + bias)));
    }
}

// ---------------------------------------------------------------------------
// inputs (metadata order): x, idx, W, gamma, beta, fc_w, fc_b
// ---------------------------------------------------------------------------
extern "C" void kernel_launch(void* const* d_in, const int* in_sizes, int n_in,
                              void* d_out, int out_size)
{
    const float* x     = (const float*)d_in[0];
    // d_in[1] = idx (identity arange by construction; unused)
    const float* W     = (const float*)d_in[2];
    const float* gamma = (const float*)d_in[3];
    const float* beta  = (const float*)d_in[4];
    const float* fc_w  = (const float*)d_in[5];
    const float* fc_b  = (const float*)d_in[6];
    float*       out   = (float*)d_out;

    k1_reps<<<BT * 8, 256>>>(x, W);          // 8192 blocks, 4 rows each

    // k2, k3 as programmatic dependents: launch prologue overlaps the
    // predecessor's tail; cudaGridDependencySynchronize() inside each kernel
    // preserves ordering of all data reads.
    cudaLaunchAttribute attr[1];
    attr[0].id = cudaLaunchAttributeProgrammaticStreamSerialization;
    attr[0].val.programmaticStreamSerializationAllowed = 1;

    {
        cudaLaunchConfig_t cfg = {};
        cfg.gridDim  = dim3(16);
        cfg.blockDim = dim3(512);
        cfg.attrs    = attr;
        cfg.numAttrs = 1;
        cudaLaunchKernelEx(&cfg, k2_stats, gamma, beta, fc_w);
    }
    {
        cudaLaunchConfig_t cfg = {};
        cfg.gridDim  = dim3(B / 16);
        cfg.blockDim = dim3(256);
        cfg.attrs    = attr;
        cfg.numAttrs = 1;
        cudaLaunchKernelEx(&cfg, k3_out, fc_b, out);
    }
}

// round 14
// speedup vs baseline: 1.0231x; 1.0231x over previous
#include <cuda_runtime.h>
#include <cuda_bf16.h>

#define B 4096
#define G 512
#define D 64
#define P (G * D)
#define EPS 1e-5f
#define NEG_SLOPE 0.2f

#define BT 512              // number of b-tiles (8 rows each)

// scratch
__device__ float g_reps[(size_t)B * G];       // [B, G] row-major, 8 MB
__device__ float g_bsum [BT][G];              // per-btile partial sums  (1 MB)
__device__ float g_bsum2[BT][G];              // per-btile partial sumsq (1 MB)
__device__ float g_a[G];
__device__ float g_csum_part[16];             // per-k2-block partial sum of c[g] (+fc_b in [0])

// L2 evict-last store via cache-hint policy register (sm_103-legal encoding).
__device__ __forceinline__ unsigned long long mk_evict_last_policy() {
    unsigned long long pol;
    asm volatile("createpolicy.fractional.L2::evict_last.b64 %0, 1.0;" : "=l"(pol));
    return pol;
}
__device__ __forceinline__ void st_evict_last(float* p, float v,
                                              unsigned long long pol) {
    asm volatile("st.global.L2::cache_hint.f32 [%0], %1, %2;"
                 :: "l"(p), "f"(v), "l"(pol) : "memory");
}

// ---------------------------------------------------------------------------
// Kernel 1: reps[b,g] = leakyrelu( dot(x[b, g*64 : g*64+64], W[g]) )
// idx is identity (arange) by construction -> direct addressing.
// Block = (btile, gtile): 8 b-rows x 64 groups. W slice register-resident,
// reused across the 8 rows. 4 threads per group, 2-step segmented shfl
// reduce. Per-btile partial stats, deterministic, no atomics.
// x streamed once (__ldcs); reps/bsum stored evict-last.
// EXACT R12 core — best measured (81.5us, 83.9% DRAM). FROZEN.
// ---------------------------------------------------------------------------
__global__ void __launch_bounds__(256) k1_reps(
    const float* __restrict__ x,
    const float* __restrict__ W)
{
    const int t     = threadIdx.x;
    const int q     = t & 3;                       // slot phase within group
    const int btile = blockIdx.x >> 3;             // 0..511
    const int gtile = blockIdx.x & 7;              // 0..7
    const int g     = (gtile << 6) + (t >> 2);     // group id
    const int b0    = btile << 3;                  // first of 8 rows

    const unsigned long long pol = mk_evict_last_policy();

    // W slice for this group: 64 floats = 4 float4, register-resident
    const float4* wp = (const float4*)(W + g * D) + q;
    const float4 w0 = __ldg(wp);
    const float4 w1 = __ldg(wp + 4);
    const float4 w2 = __ldg(wp + 8);
    const float4 w3 = __ldg(wp + 12);

    float s = 0.0f, s2 = 0.0f;

    #pragma unroll 2
    for (int i = 0; i < 8; ++i) {
        const int b = b0 + i;
        const float4* xp = (const float4*)(x + (size_t)b * P + g * D) + q;
        const float4 x0 = __ldcs(xp);
        const float4 x1 = __ldcs(xp + 4);
        const float4 x2 = __ldcs(xp + 8);
        const float4 x3 = __ldcs(xp + 12);

        float a0 = fmaf(x0.x, w0.x, x0.y * w0.y);
        a0 = fmaf(x0.z, w0.z, a0); a0 = fmaf(x0.w, w0.w, a0);
        float a1 = fmaf(x1.x, w1.x, x1.y * w1.y);
        a1 = fmaf(x1.z, w1.z, a1); a1 = fmaf(x1.w, w1.w, a1);
        float a2 = fmaf(x2.x, w2.x, x2.y * w2.y);
        a2 = fmaf(x2.z, w2.z, a2); a2 = fmaf(x2.w, w2.w, a2);
        float a3 = fmaf(x3.x, w3.x, x3.y * w3.y);
        a3 = fmaf(x3.z, w3.z, a3); a3 = fmaf(x3.w, w3.w, a3);

        float acc = (a0 + a1) + (a2 + a3);
        // butterfly over the 4-lane segment: all 4 lanes get the full dot
        acc += __shfl_xor_sync(0xffffffffu, acc, 1);
        acc += __shfl_xor_sync(0xffffffffu, acc, 2);

        acc = (acc >= 0.0f) ? acc : NEG_SLOPE * acc;
        if (q == 0) st_evict_last(&g_reps[(size_t)b * G + g], acc, pol);

        s  += acc;
        s2 += acc * acc;
    }

    if (q == 0) {
        st_evict_last(&g_bsum [btile][g], s,  pol);
        st_evict_last(&g_bsum2[btile][g], s2, pol);
    }
}

// ---------------------------------------------------------------------------
// Kernel 2: reduce 512 per-btile partials per group -> a[g]; also emit this
// block's partial sum of c[g]; block 0 folds fc_b in.
// grid = 16 blocks x 32 groups; 512 threads: lane = group (coalesced),
// 16 warps stride the btile dimension. Deterministic fixed-order reduction.
// logit[b] = sum_g a[g]*reps[b,g] + sum_g c[g] + fc_b
// ---------------------------------------------------------------------------
__global__ void __launch_bounds__(512) k2_stats(
    const float* __restrict__ gamma,
    const float* __restrict__ beta,
    const float* __restrict__ fc_w,
    const float* __restrict__ fc_b)
{
    cudaGridDependencySynchronize();   // PDL: wait for k1 results

    const int lane = threadIdx.x & 31;
    const int w    = threadIdx.x >> 5;           // 0..15
    const int g    = blockIdx.x * 32 + lane;

    float s = 0.0f, s2 = 0.0f;
    #pragma unroll 8
    for (int bt = w; bt < BT; bt += 16) {
        s  += g_bsum [bt][g];
        s2 += g_bsum2[bt][g];
    }

    __shared__ float sh[16][32];
    __shared__ float sh2[16][32];
    sh[w][lane] = s; sh2[w][lane] = s2;
    __syncthreads();

    if (w == 0) {
        float a = 0.0f, a2 = 0.0f;
        #pragma unroll
        for (int i = 0; i < 16; i++) { a += sh[i][lane]; a2 += sh2[i][lane]; }
        float mean = a * (1.0f / B);
        float var  = a2 * (1.0f / B) - mean * mean;
        float inv  = rsqrtf(var + EPS);
        float fw   = fc_w[g];
        float gm   = gamma[g];
        g_a[g] = fw * gm * inv;
        float c = fw * (beta[g] - gm * mean * inv);
        // partial sum of c over this block's 32 groups
        #pragma unroll
        for (int o = 16; o > 0; o >>= 1)
            c += __shfl_xor_sync(0xffffffffu, c, o);
        if (lane == 0)
            g_csum_part[blockIdx.x] = c + (blockIdx.x == 0 ? fc_b[0] : 0.0f);
    }
}

// ---------------------------------------------------------------------------
// Kernel 3: logit[b] = sum_g a[g]*reps[b,g] + csum, sigmoid.
// Grid = 128 blocks x 512 threads: SINGLE WAVE on 148 SMs (256-block shape
// ran 148+108 = two waves, doubling effective latency). Warp-level work
// identical to the proven R6 shape: 2 rows per warp, 12 LDG.128 in flight.
// ---------------------------------------------------------------------------
__global__ void __launch_bounds__(512) k3_out(float* __restrict__ out)
{
    cudaGridDependencySynchronize();   // PDL: wait for k2 (and k1) results

    const int lane = threadIdx.x & 31;
    const int w    = threadIdx.x >> 5;            // 0..15
    const int b    = blockIdx.x * 16 + w;         // 0..2047
    const int b2   = b + 2048;

    const float4* r4a = (const float4*)(g_reps + (size_t)b  * G);
    const float4* r4b = (const float4*)(g_reps + (size_t)b2 * G);
    const float4* a4  = (const float4*)g_a;

    float acc1 = 0.0f, acc2 = 0.0f;
    #pragma unroll
    for (int i = 0; i < 4; ++i) {
        const int j = i * 32 + lane;
        const float4 a  = __ldg(a4 + j);
        const float4 ra = __ldg(r4a + j);
        const float4 rb = __ldg(r4b + j);
        acc1 = fmaf(a.x, ra.x, acc1); acc2 = fmaf(a.x, rb.x, acc2);
        acc1 = fmaf(a.y, ra.y, acc1); acc2 = fmaf(a.y, rb.y, acc2);
        acc1 = fmaf(a.z, ra.z, acc1); acc2 = fmaf(a.z, rb.z, acc2);
        acc1 = fmaf(a.w, ra.w, acc1); acc2 = fmaf(a.w, rb.w, acc2);
    }

    // fold the c-sum partials (16 values, incl. fc_b) into both reductions
    if (lane < 16) {
        const float cp = g_csum_part[lane];
        acc1 += cp;
        acc2 += cp;
    }

    #pragma unroll
    for (int o = 16; o > 0; o >>= 1) {
        acc1 += __shfl_xor_sync(0xffffffffu, acc1, o);
        acc2 += __shfl_xor_sync(0xffffffffu, acc2, o);
    }

    if (lane == 0) {
        out[b]  = 1.0f / (1.0f + expf(-acc1));
        out[b2] = 1.0f / (1.0f + expf(-acc2));
    }
}

// ---------------------------------------------------------------------------
// inputs (metadata order): x, idx, W, gamma, beta, fc_w, fc_b
// ---------------------------------------------------------------------------
extern "C" void kernel_launch(void* const* d_in, const int* in_sizes, int n_in,
                              void* d_out, int out_size)
{
    const float* x     = (const float*)d_in[0];
    // d_in[1] = idx (identity arange by construction; unused)
    const float* W     = (const float*)d_in[2];
    const float* gamma = (const float*)d_in[3];
    const float* beta  = (const float*)d_in[4];
    const float* fc_w  = (const float*)d_in[5];
    const float* fc_b  = (const float*)d_in[6];
    float*       out   = (float*)d_out;

    k1_reps<<<BT * 8, 256>>>(x, W);          // 4096 blocks, 8 rows each

    // k2, k3 as programmatic dependents: launch prologue overlaps the
    // predecessor's tail; cudaGridDependencySynchronize() inside each kernel
    // preserves ordering of all data reads.
    cudaLaunchAttribute attr[1];
    attr[0].id = cudaLaunchAttributeProgrammaticStreamSerialization;
    attr[0].val.programmaticStreamSerializationAllowed = 1;

    {
        cudaLaunchConfig_t cfg = {};
        cfg.gridDim  = dim3(16);
        cfg.blockDim = dim3(512);
        cfg.attrs    = attr;
        cfg.numAttrs = 1;
        cudaLaunchKernelEx(&cfg, k2_stats, gamma, beta, fc_w, fc_b);
    }
    {
        cudaLaunchConfig_t cfg = {};
        cfg.gridDim  = dim3(128);
        cfg.blockDim = dim3(512);
        cfg.attrs    = attr;
        cfg.numAttrs = 1;
        cudaLaunchKernelEx(&cfg, k3_out, out);
    }
}

// round 15
// speedup vs baseline: 1.0470x; 1.0233x over previous
#include <cuda_runtime.h>
#include <cuda_bf16.h>

#define B 4096
#define G 512
#define D 64
#define P (G * D)
#define EPS 1e-5f
#define NEG_SLOPE 0.2f

#define BT 512              // number of b-tiles (8 rows each)

// scratch
__device__ float g_reps[(size_t)B * G];       // [B, G] row-major, 8 MB
__device__ float g_bsum [BT][G];              // per-btile partial sums  (1 MB)
__device__ float g_bsum2[BT][G];              // per-btile partial sumsq (1 MB)
__device__ float g_a[G];
__device__ float g_csum_part[16];             // per-k2-block partial sum of c[g]

// L2 evict-last store via cache-hint policy register (sm_103-legal encoding).
__device__ __forceinline__ unsigned long long mk_evict_last_policy() {
    unsigned long long pol;
    asm volatile("createpolicy.fractional.L2::evict_last.b64 %0, 1.0;" : "=l"(pol));
    return pol;
}
__device__ __forceinline__ void st_evict_last(float* p, float v,
                                              unsigned long long pol) {
    asm volatile("st.global.L2::cache_hint.f32 [%0], %1, %2;"
                 :: "l"(p), "f"(v), "l"(pol) : "memory");
}

// ---------------------------------------------------------------------------
// Kernel 1: reps[b,g] = leakyrelu( dot(x[b, g*64 : g*64+64], W[g]) )
// idx is identity (arange) by construction -> direct addressing.
// Block = (btile, gtile): 8 b-rows x 64 groups. W slice register-resident,
// reused across the 8 rows. 4 threads per group, 2-step segmented shfl
// reduce. Per-btile partial stats, deterministic, no atomics.
// x streamed once (__ldcs, evict-first); reps/bsum stored evict-last.
// CHAMPION CORE (81.5us, 83.9% DRAM = measured HBM ceiling). FROZEN:
// R7 reg-cap, R8/R9 sync fusion, R10 4-row k3, R13 4-row tiles all regressed.
// ---------------------------------------------------------------------------
__global__ void __launch_bounds__(256) k1_reps(
    const float* __restrict__ x,
    const float* __restrict__ W)
{
    const int t     = threadIdx.x;
    const int q     = t & 3;                       // slot phase within group
    const int btile = blockIdx.x >> 3;             // 0..511
    const int gtile = blockIdx.x & 7;              // 0..7
    const int g     = (gtile << 6) + (t >> 2);     // group id
    const int b0    = btile << 3;                  // first of 8 rows

    const unsigned long long pol = mk_evict_last_policy();

    // W slice for this group: 64 floats = 4 float4, register-resident
    const float4* wp = (const float4*)(W + g * D) + q;
    const float4 w0 = __ldg(wp);
    const float4 w1 = __ldg(wp + 4);
    const float4 w2 = __ldg(wp + 8);
    const float4 w3 = __ldg(wp + 12);

    float s = 0.0f, s2 = 0.0f;

    #pragma unroll 2
    for (int i = 0; i < 8; ++i) {
        const int b = b0 + i;
        const float4* xp = (const float4*)(x + (size_t)b * P + g * D) + q;
        const float4 x0 = __ldcs(xp);
        const float4 x1 = __ldcs(xp + 4);
        const float4 x2 = __ldcs(xp + 8);
        const float4 x3 = __ldcs(xp + 12);

        float a0 = fmaf(x0.x, w0.x, x0.y * w0.y);
        a0 = fmaf(x0.z, w0.z, a0); a0 = fmaf(x0.w, w0.w, a0);
        float a1 = fmaf(x1.x, w1.x, x1.y * w1.y);
        a1 = fmaf(x1.z, w1.z, a1); a1 = fmaf(x1.w, w1.w, a1);
        float a2 = fmaf(x2.x, w2.x, x2.y * w2.y);
        a2 = fmaf(x2.z, w2.z, a2); a2 = fmaf(x2.w, w2.w, a2);
        float a3 = fmaf(x3.x, w3.x, x3.y * w3.y);
        a3 = fmaf(x3.z, w3.z, a3); a3 = fmaf(x3.w, w3.w, a3);

        float acc = (a0 + a1) + (a2 + a3);
        // butterfly over the 4-lane segment: all 4 lanes get the full dot
        acc += __shfl_xor_sync(0xffffffffu, acc, 1);
        acc += __shfl_xor_sync(0xffffffffu, acc, 2);

        acc = (acc >= 0.0f) ? acc : NEG_SLOPE * acc;
        if (q == 0) st_evict_last(&g_reps[(size_t)b * G + g], acc, pol);

        s  += acc;
        s2 += acc * acc;
    }

    if (q == 0) {
        st_evict_last(&g_bsum [btile][g], s,  pol);
        st_evict_last(&g_bsum2[btile][g], s2, pol);
    }
}

// ---------------------------------------------------------------------------
// Kernel 2: reduce 512 per-btile partials per group -> a[g]; also emit this
// block's partial sum of c[g] (c folded out of k3's inner loop).
// grid = 16 blocks x 32 groups; 512 threads: lane = group (coalesced),
// 16 warps stride the btile dimension. Deterministic fixed-order reduction.
// logit[b] = sum_g a[g]*reps[b,g] + sum_g c[g] + fc_b
// ---------------------------------------------------------------------------
__global__ void __launch_bounds__(512) k2_stats(
    const float* __restrict__ gamma,
    const float* __restrict__ beta,
    const float* __restrict__ fc_w)
{
    cudaGridDependencySynchronize();   // PDL: wait for k1 results

    const int lane = threadIdx.x & 31;
    const int w    = threadIdx.x >> 5;           // 0..15
    const int g    = blockIdx.x * 32 + lane;

    float s = 0.0f, s2 = 0.0f;
    #pragma unroll 8
    for (int bt = w; bt < BT; bt += 16) {
        s  += g_bsum [bt][g];
        s2 += g_bsum2[bt][g];
    }

    __shared__ float sh[16][32];
    __shared__ float sh2[16][32];
    sh[w][lane] = s; sh2[w][lane] = s2;
    __syncthreads();

    if (w == 0) {
        float a = 0.0f, a2 = 0.0f;
        #pragma unroll
        for (int i = 0; i < 16; i++) { a += sh[i][lane]; a2 += sh2[i][lane]; }
        float mean = a * (1.0f / B);
        float var  = a2 * (1.0f / B) - mean * mean;
        float inv  = rsqrtf(var + EPS);
        float fw   = fc_w[g];
        float gm   = gamma[g];
        g_a[g] = fw * gm * inv;
        float c = fw * (beta[g] - gm * mean * inv);
        // partial sum of c over this block's 32 groups
        #pragma unroll
        for (int o = 16; o > 0; o >>= 1)
            c += __shfl_xor_sync(0xffffffffu, c, o);
        if (lane == 0) g_csum_part[blockIdx.x] = c;
    }
}

// ---------------------------------------------------------------------------
// Kernel 3: logit[b] = sum_g a[g]*reps[b,g] (+ csum + fc_b), sigmoid.
// 2 b-rows per warp (b and b+2048), grid = 256 blocks (best-measured shape;
// R10 4-row and R14 single-wave variants were neutral-to-worse).
// ---------------------------------------------------------------------------
__global__ void __launch_bounds__(256) k3_out(
    const float* __restrict__ fc_b,
    float* __restrict__ out)
{
    cudaGridDependencySynchronize();   // PDL: wait for k2 (and k1) results

    const int lane = threadIdx.x & 31;
    const int w    = threadIdx.x >> 5;
    const int b    = blockIdx.x * 8 + w;          // 0..2047
    const int b2   = b + 2048;

    const float4* r4a = (const float4*)(g_reps + (size_t)b  * G);
    const float4* r4b = (const float4*)(g_reps + (size_t)b2 * G);
    const float4* a4  = (const float4*)g_a;

    float acc1 = 0.0f, acc2 = 0.0f;
    #pragma unroll
    for (int i = 0; i < 4; ++i) {
        const int j = i * 32 + lane;
        const float4 a  = __ldg(a4 + j);
        const float4 ra = __ldg(r4a + j);
        const float4 rb = __ldg(r4b + j);
        acc1 = fmaf(a.x, ra.x, acc1); acc2 = fmaf(a.x, rb.x, acc2);
        acc1 = fmaf(a.y, ra.y, acc1); acc2 = fmaf(a.y, rb.y, acc2);
        acc1 = fmaf(a.z, ra.z, acc1); acc2 = fmaf(a.z, rb.z, acc2);
        acc1 = fmaf(a.w, ra.w, acc1); acc2 = fmaf(a.w, rb.w, acc2);
    }

    // fold the c-sum partials (16 values) into both reductions
    if (lane < 16) {
        const float cp = g_csum_part[lane];
        acc1 += cp;
        acc2 += cp;
    }

    #pragma unroll
    for (int o = 16; o > 0; o >>= 1) {
        acc1 += __shfl_xor_sync(0xffffffffu, acc1, o);
        acc2 += __shfl_xor_sync(0xffffffffu, acc2, o);
    }

    if (lane == 0) {
        const float bias = fc_b[0];
        // __expf: rel err ~5e-7, three orders below the 1e-3 threshold
        out[b]  = 1.0f / (1.0f + __expf(-(acc1 + bias)));
        out[b2] = 1.0f / (1.0f + __expf(-(acc2 + bias)));
    }
}

// ---------------------------------------------------------------------------
// inputs (metadata order): x, idx, W, gamma, beta, fc_w, fc_b
// ---------------------------------------------------------------------------
extern "C" void kernel_launch(void* const* d_in, const int* in_sizes, int n_in,
                              void* d_out, int out_size)
{
    const float* x     = (const float*)d_in[0];
    // d_in[1] = idx (identity arange by construction; unused)
    const float* W     = (const float*)d_in[2];
    const float* gamma = (const float*)d_in[3];
    const float* beta  = (const float*)d_in[4];
    const float* fc_w  = (const float*)d_in[5];
    const float* fc_b  = (const float*)d_in[6];
    float*       out   = (float*)d_out;

    k1_reps<<<BT * 8, 256>>>(x, W);          // 4096 blocks, 8 rows each

    // k2, k3 as programmatic dependents: launch prologue overlaps the
    // predecessor's tail; cudaGridDependencySynchronize() inside each kernel
    // preserves ordering of all data reads.
    cudaLaunchAttribute attr[1];
    attr[0].id = cudaLaunchAttributeProgrammaticStreamSerialization;
    attr[0].val.programmaticStreamSerializationAllowed = 1;

    {
        cudaLaunchConfig_t cfg = {};
        cfg.gridDim  = dim3(16);
        cfg.blockDim = dim3(512);
        cfg.attrs    = attr;
        cfg.numAttrs = 1;
        cudaLaunchKernelEx(&cfg, k2_stats, gamma, beta, fc_w);
    }
    {
        cudaLaunchConfig_t cfg = {};
        cfg.gridDim  = dim3(B / 16);
        cfg.blockDim = dim3(256);
        cfg.attrs    = attr;
        cfg.numAttrs = 1;
        cudaLaunchKernelEx(&cfg, k3_out, fc_b, out);
    }
}